// round 12
// baseline (speedup 1.0000x reference)
#include <cuda_runtime.h>

#define FULLMASK 0xffffffffu

constexpr int   B_     = 256;
constexpr int   T_     = 256;
constexpr int   C_     = 1024;
constexpr int   L_     = 32;
constexpr int   BLANK_ = C_ - 1;
constexpr int   GP_    = 11;      // float4 groups per row (lanes 0..10)
constexpr int   RF_    = 44;      // floats per row (11 groups x 4)
constexpr float PRE    = 512.0f;  // 2^9 per-step prescale
constexpr int   PRE_E  = 9;
constexpr float EPS    = 1e-7f;
constexpr float EPS_S  = EPS * PRE;

// transposed compact scratch: row (b,t) = 11 groups of
// [lab(3L), lab(3L+1), lab(3L+2), blank]   (group 10 slot 2 = 0 pad)
__device__ float g_scr[(size_t)B_ * T_ * RF_];

__device__ __forceinline__ float ldg_cg(const float* p) {
    float v;
    asm volatile("ld.global.cg.f32 %0, [%1];" : "=f"(v) : "l"(p));
    return v;
}

// exact power-of-2 renorm over 6 regs, lanes 0..10 (mask 0x7FF)
__device__ __forceinline__ int renorm6(float& r0, float& r1, float& r2,
                                       float& r3, float& r4, float& r5) {
    float m = fmaxf(fmaxf(fmaxf(r0, r1), fmaxf(r2, r3)), fmaxf(r4, r5));
    int im = __float_as_int(m);
    asm volatile("redux.sync.max.s32 %0, %1, 0x7ff;" : "=r"(im) : "r"(im));
    const int e = (im >> 23) - 127;
    const float sc = __int_as_float((127 - e) << 23);  // exact 2^-e
    r0 *= sc; r1 *= sc; r2 *= sc; r3 *= sc; r4 *= sc; r5 *= sc;
    return e;
}

// ---------------------------------------------------------------------------
// Kernel 1: saturating gather, writes the transposed group layout.
// CTA = (batch, 32-row chunk). 2048 CTAs x 256 threads, 6 items/thread.
// ---------------------------------------------------------------------------
__global__ __launch_bounds__(256)
void ctc_gather_kernel(const int* __restrict__ y_true,
                       const float* __restrict__ y_pred)
{
    __shared__ int labsx[33];   // [blank, lab0..lab31]

    const int bid   = blockIdx.x;
    const int b     = bid >> 3;
    const int chunk = (bid & 7) << 5;
    const int tid   = threadIdx.x;

    if (tid < 33)
        labsx[tid] = tid ? __ldg(y_true + b * L_ + tid - 1) : BLANK_;
    __syncthreads();

    const float* base = y_pred + ((size_t)b * T_ + chunk) * C_;

    // 32 rows x 44 items = 1408; item w: w<32 label w, 32..42 blank, 43 zero
    float v[6];
    int   rr[6], oo[6];
#pragma unroll
    for (int i = 0; i < 6; ++i) {
        const int f = tid + i * 256;
        if (f < 1408) {
            const int row = f / 44;
            const int w   = f - 44 * row;
            rr[i] = row;
            int off, cls;
            if (w < 32)      { const int g = w / 3; off = g * 4 + (w - 3 * g); cls = labsx[1 + w]; }
            else if (w < 43) { off = (w - 32) * 4 + 3; cls = labsx[0]; }
            else             { off = 42; cls = -1; }
            oo[i] = (w < 43) ? off : -off;          // sign marks zero-store
            v[i]  = (w < 43) ? ldg_cg(base + (size_t)row * C_ + cls) : 0.0f;
        }
    }
    float* orow = g_scr + ((size_t)b * T_ + chunk) * RF_;
#pragma unroll
    for (int i = 0; i < 6; ++i) {
        const int f = tid + i * 256;
        if (f < 1408) {
            if (oo[i] >= 0)
                orow[rr[i] * RF_ + oo[i]] = fmaf(v[i], PRE, EPS_S);
            else
                orow[rr[i] * RF_ - oo[i]] = 0.0f;
        }
    }
}

// ---------------------------------------------------------------------------
// Kernel 2: per-batch scan, 6 states/lane, 1 LDS.128 (+1..2 SHFL) per step.
// ---------------------------------------------------------------------------
__global__ __launch_bounds__(256)
void ctc_scan_kernel(const int* __restrict__ y_true,
                     float* __restrict__ out)
{
    __shared__ __align__(16) float slab[T_ * RF_ + 64];  // 45 KB + pad
    __shared__ int   labs[L_];
    __shared__ float exA[66], exB[66];
    __shared__ int   exE[2];

    const int b    = blockIdx.x;
    const int tid  = threadIdx.x;
    const int lane = tid & 31;
    const int wid  = tid >> 5;
    const unsigned M = 0x7FFu;

    if (tid < L_) labs[tid] = __ldg(y_true + b * L_ + tid);

    // coalesced float4 copy of this batch's 45 KB slab
    {
        const float4* src = (const float4*)(g_scr + (size_t)b * T_ * RF_);
        float4*       dst = (float4*)slab;
        for (int i = tid; i < (T_ * RF_) / 4; i += 256)
            dst[i] = src[i];
    }
    __syncthreads();

    const int Lx = lane;   // group index for active lanes
    const float4* rowp = ((const float4*)slab) + Lx;

    if (wid == 0 && lane < 11) {
        // ---------------- forward: alpha_0 .. alpha_127 ------------------
        const float a1 = (Lx == 0 || labs[3*Lx] != labs[3*Lx - 1]) ? 1.0f : 0.0f;
        const float a3 = (labs[3*Lx + 1] != labs[3*Lx]) ? 1.0f : 0.0f;
        const float a5 = (Lx < 10 && labs[3*Lx + 2] != labs[3*Lx + 1]) ? 1.0f : 0.0f;

        float r0 = 0.0f, r1 = 0.0f, r2 = 0.0f, r3 = 0.0f, r4 = 0.0f, r5 = 0.0f;
        {
            const float4 q0 = rowp[0];
            if (Lx == 0) { r0 = q0.w; r1 = q0.x; }   // alpha_0[0], alpha_0[1]
        }
        float4 q = rowp[GP_];        // row t=1
        int E = 0;

#define FSTEP(tt) {                                                   \
            const float4 qn = rowp[GP_ * ((tt) + 1)];                 \
            float u5 = __shfl_up_sync(M, r5, 1);                      \
            u5 = Lx ? u5 : 0.0f;                                      \
            const float n0 = q.w * (r0 + u5);                         \
            const float n1 = q.x * fmaf(a1, u5, r1 + r0);             \
            const float n2 = q.w * (r2 + r1);                         \
            const float n3 = q.y * fmaf(a3, r1, r3 + r2);             \
            const float n4 = q.w * (r4 + r3);                         \
            const float n5 = q.z * fmaf(a5, r3, r5 + r4);             \
            r0 = n0; r1 = n1; r2 = n2; r3 = n3; r4 = n4; r5 = n5;     \
            q = qn; }

#pragma unroll
        for (int j = 1; j < 8; ++j) FSTEP(j);
        E += renorm6(r0, r1, r2, r3, r4, r5);
        for (int tb = 8; tb < 128; tb += 8) {
#pragma unroll
            for (int j = 0; j < 8; ++j) FSTEP(tb + j);
            E += renorm6(r0, r1, r2, r3, r4, r5);
        }
#undef FSTEP

        const int s = 6 * Lx;
        exA[s]   = r0; exA[s+1] = r1; exA[s+2] = r2;
        exA[s+3] = r3; exA[s+4] = r4; exA[s+5] = r5;
        if (Lx == 0) exE[0] = E;
    }
    else if (wid == 1 && lane < 11) {
        // -------- backward: c_t = p_t * beta_t, t = 255..128 -------------
        // all labels are nonzero in this dataset, but compute len anyway
        int len = 0;
        if (Lx == 0) {
#pragma unroll
            for (int j = 0; j < L_; ++j) len += (labs[j] != 0);
        }
        len = __shfl_sync(M, len, 0);
        int ilb = 2 * len;
        int ill = 2 * len - 1;
        if (ill < 0) ill += 65;

        const float b1 = (labs[3*Lx + 1] != labs[3*Lx]) ? 1.0f : 0.0f;
        const float b3 = (Lx < 10 && labs[3*Lx + 2] != labs[3*Lx + 1]) ? 1.0f : 0.0f;
        const float b5 = (Lx < 10 && labs[3*Lx + 3] != labs[3*Lx + 2]) ? 1.0f : 0.0f;

        float r0, r1, r2, r3, r4, r5;
        {
            const float4 q0 = rowp[GP_ * 255];
            const int s = 6 * Lx;
            r0 = (s     == ilb || s     == ill) ? q0.w : 0.0f;
            r1 = (s + 1 == ilb || s + 1 == ill) ? q0.x : 0.0f;
            r2 = (s + 2 == ilb || s + 2 == ill) ? q0.w : 0.0f;
            r3 = (s + 3 == ilb || s + 3 == ill) ? q0.y : 0.0f;
            r4 = (s + 4 == ilb || s + 4 == ill) ? q0.w : 0.0f;
            r5 = (s + 5 == ilb || s + 5 == ill) ? q0.z : 0.0f;
        }
        float4 q = rowp[GP_ * 254];
        int E = 0;

#define BSTEP(tt) {                                                   \
            const float4 qn = rowp[GP_ * ((tt) - 1)];                 \
            float d0 = __shfl_down_sync(M, r0, 1);                    \
            float d1 = __shfl_down_sync(M, r1, 1);                    \
            d0 = (Lx < 10) ? d0 : 0.0f;                               \
            d1 = (Lx < 10) ? d1 : 0.0f;                               \
            const float n0 = q.w * (r0 + r1);                         \
            const float n1 = q.x * fmaf(b1, r3, r1 + r2);             \
            const float n2 = q.w * (r2 + r3);                         \
            const float n3 = q.y * fmaf(b3, r5, r3 + r4);             \
            const float n4 = q.w * (r4 + r5);                         \
            const float n5 = q.z * fmaf(b5, d1, r5 + d0);             \
            r0 = n0; r1 = n1; r2 = n2; r3 = n3; r4 = n4; r5 = n5;     \
            q = qn; }

#pragma unroll
        for (int j = 254; j > 247; --j) BSTEP(j);
        E += renorm6(r0, r1, r2, r3, r4, r5);
        for (int tb = 247; tb >= 135; tb -= 8) {
#pragma unroll
            for (int j = 0; j < 8; ++j) BSTEP(tb - j);
            E += renorm6(r0, r1, r2, r3, r4, r5);
        }
#undef BSTEP

        // beta_127 combine (no p multiply) from c_128
        float d0 = __shfl_down_sync(M, r0, 1);
        float d1 = __shfl_down_sync(M, r1, 1);
        d0 = (Lx < 10) ? d0 : 0.0f;
        d1 = (Lx < 10) ? d1 : 0.0f;
        const int s = 6 * Lx;
        exB[s]   = r0 + r1;
        exB[s+1] = fmaf(b1, r3, r1 + r2);
        exB[s+2] = r2 + r3;
        exB[s+3] = fmaf(b3, r5, r3 + r4);
        exB[s+4] = r4 + r5;
        exB[s+5] = fmaf(b5, d1, r5 + d0);
        if (Lx == 0) exE[1] = E;
    }
    __syncthreads();

    // combine: P = sum_s alpha_127[s] * beta_127[s]   (66 slots, [65] = 0)
    if (wid == 0) {
        float part = exA[lane] * exB[lane] + exA[lane + 32] * exB[lane + 32];
        if (lane < 2) part += exA[lane + 64] * exB[lane + 64];
#pragma unroll
        for (int o = 16; o; o >>= 1)
            part += __shfl_xor_sync(FULLMASK, part, o);
        if (lane == 0) {
            const float LN2 = 0.6931471805599453f;
            out[b] = -(logf(part) +
                       (float)(exE[0] + exE[1] - PRE_E * T_) * LN2);
        }
    }
}

extern "C" void kernel_launch(void* const* d_in, const int* in_sizes, int n_in,
                              void* d_out, int out_size)
{
    (void)n_in; (void)out_size;
    const int*   y_true;
    const float* y_pred;
    if (in_sizes[0] == B_ * L_) {
        y_true = (const int*)d_in[0];
        y_pred = (const float*)d_in[1];
    } else {
        y_true = (const int*)d_in[1];
        y_pred = (const float*)d_in[0];
    }
    ctc_gather_kernel<<<B_ * 8, 256>>>(y_true, y_pred);
    ctc_scan_kernel<<<B_, 256>>>(y_true, (float*)d_out);
}

// round 14
// speedup vs baseline: 1.0475x; 1.0475x over previous
#include <cuda_runtime.h>

#define FULLMASK 0xffffffffu

constexpr int   B_     = 256;
constexpr int   T_     = 256;
constexpr int   C_     = 1024;
constexpr int   L_     = 32;
constexpr int   BLANK_ = C_ - 1;
constexpr int   GP_    = 11;      // float4 groups per row
constexpr int   RF_    = 44;      // floats per row
constexpr float PRE    = 512.0f;
constexpr int   PRE_E  = 9;
constexpr float EPS    = 1e-7f;
constexpr float EPS_S  = EPS * PRE;

// transposed compact scratch: row (b,t) = 11 groups of
// [lab(3L), lab(3L+1), lab(3L+2), blank]; group 10 slot 2 = 0 pad
__device__ float g_scr[(size_t)B_ * T_ * RF_];
__device__ int   g_cnt[2][B_];        // per-(half,batch) chunk count
__device__ int   g_done[B_];          // per-batch published-half count
__device__ float g_ex[2][B_][66];     // boundary states
__device__ int   g_exE[2][B_];        // renorm exponents

__device__ __forceinline__ float ldg_cg(const float* p) {
    float v;
    asm volatile("ld.global.cg.f32 %0, [%1];" : "=f"(v) : "l"(p));
    return v;
}
__device__ __forceinline__ int renorm6(float& r0, float& r1, float& r2,
                                       float& r3, float& r4, float& r5) {
    float m = fmaxf(fmaxf(fmaxf(r0, r1), fmaxf(r2, r3)), fmaxf(r4, r5));
    int im = __float_as_int(m);
    asm volatile("redux.sync.max.s32 %0, %1, 0x7ff;" : "=r"(im) : "r"(im));
    const int e = (im >> 23) - 127;
    const float sc = __int_as_float((127 - e) << 23);  // exact 2^-e
    r0 *= sc; r1 *= sc; r2 *= sc; r3 *= sc; r4 *= sc; r5 *= sc;
    return e;
}

__global__ __launch_bounds__(256)
void ctc_fused_kernel(const int* __restrict__ y_true,
                      const float* __restrict__ y_pred,
                      float* __restrict__ out)
{
    __shared__ int   labsx[33];                       // [blank, lab0..lab31]
    // 130 rows: guard row 0, data rows 1..128, guard row 129 (prefetch slop)
    __shared__ __align__(16) float slab[130 * RF_];   // 22880 B (scan only)
    __shared__ int   s_role;

    const int bid   = blockIdx.x;
    const int b     = bid >> 3;
    const int cidx  = bid & 7;
    const int chunk = cidx << 5;
    const int half  = cidx >> 2;
    const int tid   = threadIdx.x;
    const int lane  = tid & 31;
    const int wid   = tid >> 5;

    if (tid < 33)
        labsx[tid] = tid ? __ldg(y_true + b * L_ + tid - 1) : BLANK_;
    __syncthreads();

    // ---------------- gather this CTA's 32-row chunk (transposed layout) ----
    {
        const float* base = y_pred + ((size_t)b * T_ + chunk) * C_;
        // 32 rows x 44 items; w<32: label w, 32..42: blank, 43: zero pad
        float v[6];
        int   rr[6], oo[6];
#pragma unroll
        for (int i = 0; i < 6; ++i) {
            const int f = tid + i * 256;
            if (f < 1408) {
                const int row = f / 44;
                const int w   = f - 44 * row;
                rr[i] = row;
                int off, cls;
                if (w < 32)      { const int g = w / 3; off = g * 4 + (w - 3 * g); cls = labsx[1 + w]; }
                else if (w < 43) { off = (w - 32) * 4 + 3; cls = labsx[0]; }
                else             { off = 42; cls = -1; }
                oo[i] = (w < 43) ? off : -off;
                v[i]  = (w < 43) ? ldg_cg(base + (size_t)row * C_ + cls) : 0.0f;
            }
        }
        float* orow = g_scr + ((size_t)b * T_ + chunk) * RF_;
#pragma unroll
        for (int i = 0; i < 6; ++i) {
            const int f = tid + i * 256;
            if (f < 1408) {
                if (oo[i] >= 0)
                    orow[rr[i] * RF_ + oo[i]] = fmaf(v[i], PRE, EPS_S);
                else
                    orow[rr[i] * RF_ - oo[i]] = 0.0f;
            }
        }
    }
    __threadfence();
    __syncthreads();

    // ---------------- last arriver of this half scans it ---------------------
    if (tid == 0)
        s_role = (atomicAdd(&g_cnt[half][b], 1) == 3);
    __syncthreads();
    if (!s_role) return;

    // copy this half's 128 rows (L2-hot) into smem data rows 1..128
    {
        const float4* src =
            (const float4*)(g_scr + ((size_t)b * T_ + 128 * half) * RF_);
        float4* dst = ((float4*)slab) + GP_;      // skip guard row 0
        for (int i = tid; i < 128 * GP_; i += 256)
            dst[i] = src[i];
    }
    __syncthreads();
    if (wid != 0) return;

    const unsigned M = 0x7FFu;
    const int* labs = labsx + 1;
    const int Lx = lane;
    // rowp[GP_*r] = local data row r (r in 0..127); rows -1 and 128 hit guards
    const float4* rowp = ((const float4*)slab) + GP_ + Lx;

    // len for backward init (full warp)
    const unsigned nzm = __ballot_sync(FULLMASK, labsx[1 + lane] != 0);
    const int len = __popc(nzm);

    float R0 = 0, R1 = 0, R2 = 0, R3 = 0, R4 = 0, R5 = 0;
    int   E  = 0;

    if (lane < 11) {
        float r0 = 0.0f, r1 = 0.0f, r2 = 0.0f, r3 = 0.0f, r4 = 0.0f, r5 = 0.0f;

        if (half == 0) {
            // -------- forward: alpha_0 .. alpha_127 (local rows 0..127) -----
            const float a1 = (Lx == 0 || labs[3*Lx] != labs[3*Lx - 1]) ? 1.0f : 0.0f;
            const float a3 = (labs[3*Lx + 1] != labs[3*Lx]) ? 1.0f : 0.0f;
            const float a5 = (Lx < 10 && labs[3*Lx + 2] != labs[3*Lx + 1]) ? 1.0f : 0.0f;

            {
                const float4 q0 = rowp[0];
                if (Lx == 0) { r0 = q0.w; r1 = q0.x; }
            }
            float4 q = rowp[GP_];

#define FSTEP(tt) {                                                   \
                const float4 qn = rowp[GP_ * ((tt) + 1)];             \
                float u5 = __shfl_up_sync(M, r5, 1);                  \
                u5 = Lx ? u5 : 0.0f;                                  \
                const float n0 = q.w * (r0 + u5);                     \
                const float n1 = q.x * fmaf(a1, u5, r1 + r0);         \
                const float n2 = q.w * (r2 + r1);                     \
                const float n3 = q.y * fmaf(a3, r1, r3 + r2);         \
                const float n4 = q.w * (r4 + r3);                     \
                const float n5 = q.z * fmaf(a5, r3, r5 + r4);         \
                r0 = n0; r1 = n1; r2 = n2; r3 = n3; r4 = n4; r5 = n5; \
                q = qn; }

#pragma unroll
            for (int j = 1; j < 8; ++j) FSTEP(j);
            E += renorm6(r0, r1, r2, r3, r4, r5);
            for (int tb = 8; tb < 128; tb += 8) {
#pragma unroll
                for (int j = 0; j < 8; ++j) FSTEP(tb + j);
                E += renorm6(r0, r1, r2, r3, r4, r5);
            }
#undef FSTEP
            R0 = r0; R1 = r1; R2 = r2; R3 = r3; R4 = r4; R5 = r5;
        } else {
            // ---- backward: c_t = p_t*beta_t, global t=255..128 (local 127..0)
            int ilb = 2 * len;
            int ill = 2 * len - 1;
            if (ill < 0) ill += 65;

            const float b1 = (labs[3*Lx + 1] != labs[3*Lx]) ? 1.0f : 0.0f;
            const float b3 = (Lx < 10 && labs[3*Lx + 2] != labs[3*Lx + 1]) ? 1.0f : 0.0f;
            const float b5 = (Lx < 10 && labs[3*Lx + 3] != labs[3*Lx + 2]) ? 1.0f : 0.0f;

            {
                const float4 q0 = rowp[GP_ * 127];    // global t = 255
                const int s = 6 * Lx;
                r0 = (s     == ilb || s     == ill) ? q0.w : 0.0f;
                r1 = (s + 1 == ilb || s + 1 == ill) ? q0.x : 0.0f;
                r2 = (s + 2 == ilb || s + 2 == ill) ? q0.w : 0.0f;
                r3 = (s + 3 == ilb || s + 3 == ill) ? q0.y : 0.0f;
                r4 = (s + 4 == ilb || s + 4 == ill) ? q0.w : 0.0f;
                r5 = (s + 5 == ilb || s + 5 == ill) ? q0.z : 0.0f;
            }
            float4 q = rowp[GP_ * 126];

#define BSTEP(tt) {                                                   \
                const float4 qn = rowp[GP_ * ((tt) - 1)];             \
                float d0 = __shfl_down_sync(M, r0, 1);                \
                float d1 = __shfl_down_sync(M, r1, 1);                \
                d0 = (Lx < 10) ? d0 : 0.0f;                           \
                d1 = (Lx < 10) ? d1 : 0.0f;                           \
                const float n0 = q.w * (r0 + r1);                     \
                const float n1 = q.x * fmaf(b1, r3, r1 + r2);         \
                const float n2 = q.w * (r2 + r3);                     \
                const float n3 = q.y * fmaf(b3, r5, r3 + r4);         \
                const float n4 = q.w * (r4 + r5);                     \
                const float n5 = q.z * fmaf(b5, d1, r5 + d0);         \
                r0 = n0; r1 = n1; r2 = n2; r3 = n3; r4 = n4; r5 = n5; \
                q = qn; }

#pragma unroll
            for (int j = 126; j > 119; --j) BSTEP(j);
            E += renorm6(r0, r1, r2, r3, r4, r5);
            for (int tb = 119; tb >= 7; tb -= 8) {
#pragma unroll
                for (int j = 0; j < 8; ++j) BSTEP(tb - j);
                E += renorm6(r0, r1, r2, r3, r4, r5);
            }
#undef BSTEP

            // beta_127 combine (no p multiply) from c_128
            float d0 = __shfl_down_sync(M, r0, 1);
            float d1 = __shfl_down_sync(M, r1, 1);
            d0 = (Lx < 10) ? d0 : 0.0f;
            d1 = (Lx < 10) ? d1 : 0.0f;
            R0 = r0 + r1;
            R1 = fmaf(b1, r3, r1 + r2);
            R2 = r2 + r3;
            R3 = fmaf(b3, r5, r3 + r4);
            R4 = r4 + r5;
            R5 = fmaf(b5, d1, r5 + d0);
        }

        // publish boundary state
        const int s = 6 * Lx;
        g_ex[half][b][s]     = R0;
        g_ex[half][b][s + 1] = R1;
        g_ex[half][b][s + 2] = R2;
        g_ex[half][b][s + 3] = R3;
        g_ex[half][b][s + 4] = R4;
        g_ex[half][b][s + 5] = R5;
    }

    int oldd = 0;
    if (lane == 0) {
        g_exE[half][b] = E;
        __threadfence();
        oldd = atomicAdd(&g_done[b], 1);
        g_cnt[half][b] = 0;            // reset for next replay
    }
    oldd = __shfl_sync(FULLMASK, oldd, 0);

    if (oldd == 1) {
        __threadfence();
        // P = sum over 66 slots of alpha_127 * beta_127
        float part = ldg_cg(&g_ex[0][b][lane])      * ldg_cg(&g_ex[1][b][lane])
                   + ldg_cg(&g_ex[0][b][lane + 32]) * ldg_cg(&g_ex[1][b][lane + 32]);
        if (lane < 2)
            part += ldg_cg(&g_ex[0][b][lane + 64]) * ldg_cg(&g_ex[1][b][lane + 64]);
#pragma unroll
        for (int o = 16; o; o >>= 1)
            part += __shfl_xor_sync(FULLMASK, part, o);
        if (lane == 0) {
            int e0, e1;
            asm volatile("ld.global.cg.s32 %0, [%1];" : "=r"(e0) : "l"(&g_exE[0][b]));
            asm volatile("ld.global.cg.s32 %0, [%1];" : "=r"(e1) : "l"(&g_exE[1][b]));
            const float LN2 = 0.6931471805599453f;
            out[b] = -(logf(part) + (float)(e0 + e1 - PRE_E * T_) * LN2);
            g_done[b] = 0;             // reset for next replay
        }
    }
}

extern "C" void kernel_launch(void* const* d_in, const int* in_sizes, int n_in,
                              void* d_out, int out_size)
{
    (void)n_in; (void)out_size;
    const int*   y_true;
    const float* y_pred;
    if (in_sizes[0] == B_ * L_) {
        y_true = (const int*)d_in[0];
        y_pred = (const float*)d_in[1];
    } else {
        y_true = (const int*)d_in[1];
        y_pred = (const float*)d_in[0];
    }
    ctc_fused_kernel<<<B_ * 8, 256>>>(y_true, y_pred, (float*)d_out);
}